// round 16
// baseline (speedup 1.0000x reference)
#include <cuda_runtime.h>
#include <cuda_fp16.h>
#include <cstdint>
#include <math.h>

#define BATCH 8192
#define SDIM  268
#define HDIM  1024
#define RB    8
#define ADIM  256
#define ZDIM  8
#define EDIM  4
#define KX    320   /* 270 padded to multiple of 64 */

#define CDIV(a,b) (((a)+(b)-1)/(b))
#define EPI_NONE 0
#define EPI_RELU 1
#define EPI_TANH 2

// GEMM: CTA 256x128, 16 warps (4M x 4N), warp tile 64x32, K chunk 64
#define KC     64
#define RSTR   144              /* 128B data + 16B pad per row */
#define OFF_B  36864            /* A level = 256*144 */
#define STG_SZ 55296            /* A(256 rows) + B(128 rows) */
#define NSTAGE 3
#define SMEM_DYN (NSTAGE*STG_SZ)   /* 165888 B */

// ---------------------------------------------------------------------------
// Scratch (static __device__ arrays; no allocation anywhere)
// ---------------------------------------------------------------------------
__device__ __align__(16) __half g_x [BATCH*KX];
__device__ __align__(16) __half g_hA[BATCH*HDIM];
__device__ __align__(16) __half g_hB[BATCH*HDIM];
__device__ __align__(16) __half g_u [BATCH*HDIM];
__device__ __align__(16) __half g_v [BATCH*ADIM];
__device__ __align__(16) float  g_dh[BATCH*ADIM];
__device__ __align__(16) float  g_dloc[BATCH*ZDIM];

__device__ __align__(16) __half g_W0[HDIM*KX];
__device__ __align__(16) __half g_W1[RB*HDIM*HDIM];
__device__ __align__(16) __half g_W2[RB*HDIM*HDIM];
__device__ __align__(16) __half g_Wf[SDIM*HDIM];
__device__ __align__(16) __half g_TI[ADIM*ADIM];
__device__ __align__(16) __half g_TO[ADIM*ADIM];

// ---------------------------------------------------------------------------
// Helpers
// ---------------------------------------------------------------------------
__device__ __forceinline__ float tanh_fast(float x) {
    float e = __expf(2.0f * x);
    return 1.0f - __fdividef(2.0f, e + 1.0f);   // NaN-safe
}
__device__ __forceinline__ uint32_t smem_u32(const void* p) {
    uint32_t a;
    asm("{ .reg .u64 t; cvta.to.shared.u64 t, %1; cvt.u32.u64 %0, t; }" : "=r"(a) : "l"(p));
    return a;
}
__device__ __forceinline__ void ldm4(unsigned r[4], uint32_t addr) {
    asm volatile("ldmatrix.sync.aligned.m8n8.x4.shared.b16 {%0,%1,%2,%3}, [%4];"
                 : "=r"(r[0]), "=r"(r[1]), "=r"(r[2]), "=r"(r[3]) : "r"(addr));
}
__device__ __forceinline__ void mma_f16(float c[4], const unsigned a[4], const unsigned b[2]) {
    asm volatile(
        "mma.sync.aligned.m16n8k16.row.col.f32.f16.f16.f32 "
        "{%0,%1,%2,%3}, {%4,%5,%6,%7}, {%8,%9}, {%0,%1,%2,%3};"
        : "+f"(c[0]), "+f"(c[1]), "+f"(c[2]), "+f"(c[3])
        : "r"(a[0]), "r"(a[1]), "r"(a[2]), "r"(a[3]), "r"(b[0]), "r"(b[1]));
}
__device__ __forceinline__ void cpa16(uint32_t dst, const void* src, unsigned n) {
    asm volatile("cp.async.cg.shared.global [%0], [%1], 16, %2;"
                 :: "r"(dst), "l"(src), "r"(n));
}
#define CP_COMMIT() asm volatile("cp.async.commit_group;" ::: "memory")
#define CP_WAIT1()  asm volatile("cp.async.wait_group 1;"  ::: "memory")
#define CP_WAIT0()  asm volatile("cp.async.wait_group 0;"  ::: "memory")

// ---------------------------------------------------------------------------
// fp16 GEMM: C(MxN) = act( A(MxK) @ B^T + bias [+ AD] )
// CTA 256x128, 512 threads, 16 warps (4M x 4N), warp tile 64x32.
// KC=64, 3-stage cp.async, fragment double-buffering, B via x4 ldmatrix.
// ---------------------------------------------------------------------------
__global__ void __launch_bounds__(512, 1)
gemm_f16(const __half* __restrict__ A, int lda,
         const __half* __restrict__ B, int ldb,
         const float* __restrict__ bias,
         const __half* __restrict__ AD, int ldad,
         float* __restrict__ Cf, __half* __restrict__ Ch,
         int ldc, int N, int K, int epi)
{
    extern __shared__ __align__(16) char smem[];
    const uint32_t sb = smem_u32(smem);

    const int tid    = threadIdx.x;
    const int lane   = tid & 31;
    const int wid    = tid >> 5;
    const int warpM  = wid >> 2;        // 0..3
    const int warpN  = wid & 3;         // 0..3
    const int blockM = blockIdx.y * 256;
    const int blockN = blockIdx.x * 128;

    // ---- staging: A 2048 units (row=u>>3, q=u&7), B 1024 units ----
    const int rA = tid >> 3, qA = tid & 7;   // A units: tid + 512*j (j=0..3)
    // thread covers A rows rA + 64*j, same q
    const __half* pA = A + (size_t)(blockM + rA) * lda + qA * 8;
    const uint32_t dA = (uint32_t)(rA * RSTR + qA * 16);
    // B units: tid + 512*j (j=0..1): rows rA + 64*j (0..127)
    const int nG0 = blockN + rA;
    const int nG1 = blockN + rA + 64;
    const unsigned szB0 = (nG0 < N) ? 16u : 0u;
    const unsigned szB1 = (nG1 < N) ? 16u : 0u;
    const __half* pB0 = B + (size_t)(nG0 < N ? nG0 : 0) * ldb + qA * 8;
    const __half* pB1 = B + (size_t)(nG1 < N ? nG1 : 0) * ldb + qA * 8;
    const uint32_t dB = (uint32_t)(OFF_B + rA * RSTR + qA * 16);

    // ---- ldmatrix bases ----
    const uint32_t aBase = (uint32_t)((warpM * 64 + (lane & 15)) * RSTR + (lane >> 4) * 16);
    const uint32_t bBase = (uint32_t)((warpN * 32 + ((lane >> 4) << 3) + (lane & 7)) * RSTR
                                     + ((lane >> 3) & 1) * 16);

    float acc[4][4][4];
    #pragma unroll
    for (int mt = 0; mt < 4; ++mt)
        #pragma unroll
        for (int nt = 0; nt < 4; ++nt)
            #pragma unroll
            for (int i = 0; i < 4; ++i) acc[mt][nt][i] = 0.0f;

    const int nk = K / KC;

    auto stage_copy = [&](int slot, int k0) {
        const uint32_t so = sb + (uint32_t)(slot * STG_SZ);
        #pragma unroll
        for (int j = 0; j < 4; ++j)
            cpa16(so + dA + (uint32_t)(j * 64 * RSTR),
                  pA + (size_t)(64 * j) * lda + k0, 16u);
        cpa16(so + dB, pB0 + k0, szB0);
        cpa16(so + dB + (uint32_t)(64 * RSTR), pB1 + k0, szB1);
    };

    stage_copy(0, 0);   CP_COMMIT();
    stage_copy(1, KC);  CP_COMMIT();

    unsigned Af[2][4][4], Bf[2][2][4];

    for (int kt = 0; kt < nk; ++kt) {
        CP_WAIT1();
        __syncthreads();

        if (kt + 2 < nk) stage_copy((kt + 2) % NSTAGE, (kt + 2) * KC);
        CP_COMMIT();

        const uint32_t so = sb + (uint32_t)((kt % NSTAGE) * STG_SZ);

        // k-step 0 fragments
        #pragma unroll
        for (int mt = 0; mt < 4; ++mt)
            ldm4(Af[0][mt], so + aBase + (uint32_t)(mt * 16 * RSTR));
        #pragma unroll
        for (int p = 0; p < 2; ++p)
            ldm4(Bf[0][p], so + OFF_B + bBase + (uint32_t)(p * 16 * RSTR));

        #pragma unroll
        for (int ks = 0; ks < 4; ++ks) {
            const int cur = ks & 1, nxt = cur ^ 1;
            if (ks < 3) {
                #pragma unroll
                for (int mt = 0; mt < 4; ++mt)
                    ldm4(Af[nxt][mt], so + aBase + (uint32_t)(mt * 16 * RSTR + (ks + 1) * 32));
                #pragma unroll
                for (int p = 0; p < 2; ++p)
                    ldm4(Bf[nxt][p], so + OFF_B + bBase + (uint32_t)(p * 16 * RSTR + (ks + 1) * 32));
            }
            #pragma unroll
            for (int p = 0; p < 2; ++p) {
                #pragma unroll
                for (int mt = 0; mt < 4; ++mt) {
                    mma_f16(acc[mt][2 * p + 0], Af[cur][mt], &Bf[cur][p][0]);
                    mma_f16(acc[mt][2 * p + 1], Af[cur][mt], &Bf[cur][p][2]);
                }
            }
        }
    }
    CP_WAIT0();

    // ---- epilogue ----
    const int g = lane >> 2, q = lane & 3;
    #pragma unroll
    for (int mt = 0; mt < 4; ++mt) {
        #pragma unroll
        for (int nt = 0; nt < 4; ++nt) {
            const int row0 = blockM + warpM * 64 + mt * 16 + g;
            const int col  = blockN + warpN * 32 + nt * 8 + q * 2;
            const bool c0 = col < N, c1 = (col + 1) < N;
            const float b0v = c0 ? bias[col] : 0.0f;
            const float b1v = c1 ? bias[col + 1] : 0.0f;
            #pragma unroll
            for (int rr = 0; rr < 2; ++rr) {
                const int r = row0 + rr * 8;
                float v0 = acc[mt][nt][rr * 2 + 0] + b0v;
                float v1 = acc[mt][nt][rr * 2 + 1] + b1v;
                if (AD) {
                    const size_t o = (size_t)r * ldad + col;
                    if (c0) v0 += __half2float(AD[o]);
                    if (c1) v1 += __half2float(AD[o + 1]);
                }
                if (epi == EPI_RELU)      { v0 = fmaxf(v0, 0.0f); v1 = fmaxf(v1, 0.0f); }
                else if (epi == EPI_TANH) { v0 = tanh_fast(v0);   v1 = tanh_fast(v1);   }
                const size_t oc = (size_t)r * ldc + col;
                if (Cf) {
                    if (c0) Cf[oc]     = v0;
                    if (c1) Cf[oc + 1] = v1;
                } else {
                    if (c0 && c1) {
                        *(__half2*)(Ch + oc) = __floats2half2_rn(v0, v1);
                    } else if (c0) {
                        Ch[oc] = __float2half_rn(v0);
                    }
                }
            }
        }
    }
}

// ---------------------------------------------------------------------------
// Prologue: fp16 conversions
// ---------------------------------------------------------------------------
#define N_W1 (RB*HDIM*HDIM)
#define N_W2 (RB*HDIM*HDIM)
#define N_WF (SDIM*HDIM)
#define N_TT (ADIM*ADIM)
#define N_ALL (N_W1 + N_W2 + N_WF + N_TT + N_TT)

__global__ void conv_all_kernel(const float* __restrict__ rW1, const float* __restrict__ rW2,
                                const float* __restrict__ Wf,  const float* __restrict__ ta_in_w,
                                const float* __restrict__ ta_out_w)
{
    const int i4 = blockIdx.x * blockDim.x + threadIdx.x;
    const long long i = (long long)i4 * 4;
    if (i >= N_ALL) return;
    const float* src; __half* dst; long long off;
    if (i < N_W1)                           { src = rW1;                         dst = g_W1; off = i; }
    else if (i < N_W1 + N_W2)               { src = rW2;                         dst = g_W2; off = i - N_W1; }
    else if (i < N_W1 + N_W2 + N_WF)        { src = Wf;                          dst = g_Wf; off = i - N_W1 - N_W2; }
    else if (i < N_W1 + N_W2 + N_WF + N_TT) { src = ta_in_w + 2 * ADIM * ADIM;   dst = g_TI; off = i - N_W1 - N_W2 - N_WF; }
    else                                    { src = ta_out_w;                    dst = g_TO; off = i - N_W1 - N_W2 - N_WF - N_TT; }
    float4 v = *(const float4*)(src + off);
    __half2* d = (__half2*)(dst + off);
    d[0] = __floats2half2_rn(v.x, v.y);
    d[1] = __floats2half2_rn(v.z, v.w);
}

#define N_CW0 (HDIM*KX)
__global__ void prep_kernel(const float* __restrict__ W0,
                            const float* __restrict__ state, const float* __restrict__ t)
{
    int i = blockIdx.x * blockDim.x + threadIdx.x;
    if (i < N_CW0) {
        int row = i / KX, c = i % KX;
        float v = (c < SDIM + 2) ? W0[row * (SDIM + 2) + c] : 0.0f;
        g_W0[i] = __float2half_rn(v);
        return;
    }
    i -= N_CW0;
    if (i >= BATCH * KX) return;
    int b = i / KX, c = i % KX;
    float v;
    if (c < SDIM) v = state[b * SDIM + c];
    else if (c == SDIM)     { float ang = t[0] * 0.26179938779914943654f; v = sinf(ang); }
    else if (c == SDIM + 1) { float ang = t[0] * 0.26179938779914943654f; v = cosf(ang); }
    else v = 0.0f;
    g_x[i] = __float2half_rn(v);
}

// ---------------------------------------------------------------------------
// Tiny loc path (exact fp32)
// ---------------------------------------------------------------------------
__global__ void loc_kernel(const float* __restrict__ state,
                           const float* __restrict__ loc_proj_w, const float* __restrict__ loc_proj_b,
                           const float* __restrict__ lp_in_w,    const float* __restrict__ lp_in_b,
                           const float* __restrict__ lp_out_w,   const float* __restrict__ lp_out_b,
                           const float* __restrict__ loc_back_w, const float* __restrict__ loc_back_b,
                           float* __restrict__ dloc)
{
    int b = blockIdx.x * blockDim.x + threadIdx.x;
    if (b >= BATCH) return;
    float loc[ZDIM];
    #pragma unroll
    for (int z = 0; z < ZDIM; ++z) loc[z] = state[b * SDIM + ADIM + z];
    float lp[EDIM];
    #pragma unroll
    for (int e = 0; e < EDIM; ++e) {
        float s = loc_proj_b[e];
        #pragma unroll
        for (int z = 0; z < ZDIM; ++z) s += loc_proj_w[e * ZDIM + z] * loc[z];
        lp[e] = s;
    }
    float v[EDIM];
    #pragma unroll
    for (int e = 0; e < EDIM; ++e) {
        float s = lp_in_b[2 * EDIM + e];
        #pragma unroll
        for (int j = 0; j < EDIM; ++j) s += lp_in_w[(2 * EDIM + e) * EDIM + j] * lp[j];
        v[e] = s;
    }
    float d[EDIM];
    #pragma unroll
    for (int e = 0; e < EDIM; ++e) {
        float s = lp_out_b[e];
        #pragma unroll
        for (int j = 0; j < EDIM; ++j) s += lp_out_w[e * EDIM + j] * v[j];
        d[e] = s - lp[e];
    }
    #pragma unroll
    for (int z = 0; z < ZDIM; ++z) {
        float s = loc_back_b[z];
        #pragma unroll
        for (int e = 0; e < EDIM; ++e) s += loc_back_w[z * EDIM + e] * d[e];
        dloc[b * ZDIM + z] = s;
    }
}

__global__ void combine_kernel(float* __restrict__ out,
                               const float* __restrict__ state,
                               const float* __restrict__ dh,
                               const float* __restrict__ dloc)
{
    int i = blockIdx.x * blockDim.x + threadIdx.x;
    if (i >= BATCH * SDIM) return;
    int b = i / SDIM, j = i % SDIM;
    float o = out[i];
    if (j < ADIM)              o += 0.1f * (dh[b * ADIM + j] - state[i]);
    else if (j < ADIM + ZDIM)  o += 0.1f * dloc[b * ZDIM + (j - ADIM)];
    out[i] = o;
}

// ---------------------------------------------------------------------------
// Launch
// ---------------------------------------------------------------------------
extern "C" void kernel_launch(void* const* d_in, const int* in_sizes, int n_in,
                              void* d_out, int out_size)
{
    const float* t          = (const float*)d_in[0];
    const float* state      = (const float*)d_in[1];
    const float* W0         = (const float*)d_in[2];
    const float* b0         = (const float*)d_in[3];
    const float* rW1        = (const float*)d_in[4];
    const float* rb1        = (const float*)d_in[5];
    const float* rW2        = (const float*)d_in[6];
    const float* rb2        = (const float*)d_in[7];
    const float* Wf         = (const float*)d_in[8];
    const float* bf_        = (const float*)d_in[9];
    const float* lp_in_w    = (const float*)d_in[10];
    const float* lp_in_b    = (const float*)d_in[11];
    const float* lp_out_w   = (const float*)d_in[12];
    const float* lp_out_b   = (const float*)d_in[13];
    const float* ta_in_w    = (const float*)d_in[14];
    const float* ta_in_b    = (const float*)d_in[15];
    const float* ta_out_w   = (const float*)d_in[16];
    const float* ta_out_b   = (const float*)d_in[17];
    const float* loc_proj_w = (const float*)d_in[18];
    const float* loc_proj_b = (const float*)d_in[19];
    const float* loc_back_w = (const float*)d_in[20];
    const float* loc_back_b = (const float*)d_in[21];
    float* out = (float*)d_out;

    __half *x, *hA, *hB, *u, *v;
    float *dh, *dloc;
    __half *W0h, *W1h, *W2h, *Wfh, *TIh, *TOh;
    cudaGetSymbolAddress((void**)&x,  g_x);
    cudaGetSymbolAddress((void**)&hA, g_hA);
    cudaGetSymbolAddress((void**)&hB, g_hB);
    cudaGetSymbolAddress((void**)&u,  g_u);
    cudaGetSymbolAddress((void**)&v,  g_v);
    cudaGetSymbolAddress((void**)&dh, g_dh);
    cudaGetSymbolAddress((void**)&dloc, g_dloc);
    cudaGetSymbolAddress((void**)&W0h, g_W0);
    cudaGetSymbolAddress((void**)&W1h, g_W1);
    cudaGetSymbolAddress((void**)&W2h, g_W2);
    cudaGetSymbolAddress((void**)&Wfh, g_Wf);
    cudaGetSymbolAddress((void**)&TIh, g_TI);
    cudaGetSymbolAddress((void**)&TOh, g_TO);

    cudaFuncSetAttribute(gemm_f16, cudaFuncAttributeMaxDynamicSharedMemorySize, SMEM_DYN);

    // --- prologue (2 launches) ---
    conv_all_kernel<<<CDIV(N_ALL / 4, 256), 256>>>(rW1, rW2, Wf, ta_in_w, ta_out_w);
    prep_kernel<<<CDIV(N_CW0 + BATCH * KX, 256), 256>>>(W0, state, t);

    // --- main chain ---
    dim3 blk(512);
    dim3 gH(HDIM / 128, BATCH / 256);           // (8, 32)

    // h = relu(x @ W0^T + b0)
    gemm_f16<<<gH, blk, SMEM_DYN>>>(x, KX, W0h, KX, b0, nullptr, 0,
                                    nullptr, hA, HDIM, HDIM, KX, EPI_RELU);

    __half *hc = hA, *hn = hB;
    for (int i = 0; i < RB; ++i) {
        const size_t wo = (size_t)i * HDIM * HDIM;
        // u = tanh(h @ W1^T + b1)
        gemm_f16<<<gH, blk, SMEM_DYN>>>(hc, HDIM, W1h + wo, HDIM, rb1 + i * HDIM,
                                        nullptr, 0,
                                        nullptr, u, HDIM, HDIM, HDIM, EPI_TANH);
        // h' = tanh(u @ W2^T + b2 + h)
        gemm_f16<<<gH, blk, SMEM_DYN>>>(u, HDIM, W2h + wo, HDIM, rb2 + i * HDIM,
                                        hc, HDIM,
                                        nullptr, hn, HDIM, HDIM, HDIM, EPI_TANH);
        __half* tmp = hc; hc = hn; hn = tmp;
    }

    // core = h @ Wf^T + bf -> f32 out
    dim3 gF(CDIV(SDIM, 128), BATCH / 256);      // (3, 32)
    gemm_f16<<<gF, blk, SMEM_DYN>>>(hc, HDIM, Wfh, HDIM, bf_, nullptr, 0,
                                    out, nullptr, SDIM, SDIM, HDIM, EPI_NONE);

    // --- independent side path (h_part = first 256 cols of x) ---
    dim3 gT(ADIM / 128, BATCH / 256);           // (2, 32)
    gemm_f16<<<gT, blk, SMEM_DYN>>>(x, KX, TIh, ADIM, ta_in_b + 2 * ADIM, nullptr, 0,
                                    nullptr, v, ADIM, ADIM, ADIM, EPI_NONE);
    gemm_f16<<<gT, blk, SMEM_DYN>>>(v, ADIM, TOh, ADIM, ta_out_b, nullptr, 0,
                                    dh, nullptr, ADIM, ADIM, ADIM, EPI_NONE);
    loc_kernel<<<CDIV(BATCH, 256), 256>>>(state, loc_proj_w, loc_proj_b,
                                          lp_in_w, lp_in_b, lp_out_w, lp_out_b,
                                          loc_back_w, loc_back_b, dloc);

    combine_kernel<<<CDIV(BATCH * SDIM, 256), 256>>>(out, state, dh, dloc);
}